// round 13
// baseline (speedup 1.0000x reference)
#include <cuda_runtime.h>
#include <cstdint>

#define N_COLS 24576
#define K_TOP 64
#define THREADS 512
#define F4_PER_THREAD 12   // 24576 / 4 / 512
#define SEG 64             // candidate slots per warp
#define CAP 1024           // 16 warps * 64 slots
#define CPL 32             // slots per lane in warp-0 scan (CAP/32)
#define T0 2.2f

// Monotonic key: larger float -> larger unsigned key
__device__ __forceinline__ unsigned fkey(float x) {
    unsigned u = __float_as_uint(x);
    return (u & 0x80000000u) ? ~u : (u | 0x80000000u);
}

__global__ __launch_bounds__(THREADS, 3)
void topk_fused(const float* __restrict__ x, float* __restrict__ out) {
    __shared__ unsigned sKey[CAP];
    __shared__ unsigned sIdx[CAP];
    __shared__ unsigned sCnt[16];

    const int row = blockIdx.x;
    const float4* __restrict__ xr = (const float4*)(x + (size_t)row * N_COLS);
    float4* __restrict__ orow4 = (float4*)(out + (size_t)row * N_COLS);
    float* __restrict__ orow = out + (size_t)row * N_COLS;
    const int tid = threadIdx.x;
    const int lane = tid & 31;
    const int wid = tid >> 5;
    const int seg = wid * SEG;
    const unsigned lmask = (1u << lane) - 1u;

    // zero own segment's keys (holes must read as 0); warp-local, no barrier needed
    sKey[seg + lane] = 0u;
    sKey[seg + 32 + lane] = 0u;

    const float4 zero4 = make_float4(0.f, 0.f, 0.f, 0.f);
    unsigned wcnt = 0;   // warp-uniform candidate count

    // ---- Phase 1: stream row, write zeros, ballot-compact candidates x > T0 ----
    #pragma unroll
    for (int g = 0; g < F4_PER_THREAD / 4; g++) {
        float4 v[4];
        #pragma unroll
        for (int j = 0; j < 4; j++)
            v[j] = xr[tid + (g * 4 + j) * THREADS];

        #pragma unroll
        for (int j = 0; j < 4; j++)
            __stcs(&orow4[tid + (g * 4 + j) * THREADS], zero4);

        #pragma unroll
        for (int j = 0; j < 4; j++) {
            float vals[4] = {v[j].x, v[j].y, v[j].z, v[j].w};
            #pragma unroll
            for (int c = 0; c < 4; c++) {
                bool hit = vals[c] > T0;
                unsigned m = __ballot_sync(0xffffffffu, hit);
                if (m) {
                    if (hit) {
                        unsigned off = wcnt + (unsigned)__popc(m & lmask);
                        if (off < SEG) {
                            sKey[seg + off] = fkey(vals[c]);
                            sIdx[seg + off] = (unsigned)((tid + (g * 4 + j) * THREADS) * 4 + c);
                        }
                    }
                    wcnt += (unsigned)__popc(m);
                }
            }
        }
    }
    if (lane == 0) sCnt[wid] = wcnt;
    __syncthreads();

    // ---- Phase 2: warp 0 selects + scatters; other warps retire ----
    if (tid >= 32) return;

    unsigned myCnt = (lane < 16) ? sCnt[lane] : 0u;
    unsigned nc = __reduce_add_sync(0xffffffffu, myCnt);
    bool overflow = __ballot_sync(0xffffffffu, myCnt > SEG) != 0u;

    const unsigned T0KEY = fkey(T0);

    if (nc >= K_TOP && !overflow) {
        // ============ FAST PATH (warp-local, barrier-free) ============
        // Holes hold key 0 (< T0KEY), invisible to all predicates below.
        unsigned key[CPL];
        #pragma unroll
        for (int j = 0; j < CPL; j++)
            key[j] = sKey[lane + j * 32];

        unsigned wmax = 0;
        #pragma unroll
        for (int j = 0; j < CPL; j++) wmax = max(wmax, key[j]);
        wmax = __reduce_max_sync(0xffffffffu, wmax);

        // binary search: smallest T with count(key > T) < K  ==> T = kth key
        unsigned lo = T0KEY, hi = wmax;
        while (lo < hi) {
            unsigned mid = lo + ((hi - lo) >> 1);
            unsigned c = 0;
            #pragma unroll
            for (int j = 0; j < CPL; j++) c += (key[j] > mid) ? 1u : 0u;
            c = __reduce_add_sync(0xffffffffu, c);
            if (c < K_TOP) hi = mid; else lo = mid + 1;
        }
        const unsigned kth = lo;

        unsigned cgt = 0, ceq = 0;
        #pragma unroll
        for (int j = 0; j < CPL; j++) {
            cgt += (key[j] > kth) ? 1u : 0u;
            ceq += (key[j] == kth) ? 1u : 0u;
        }
        cgt = __reduce_add_sync(0xffffffffu, cgt);
        ceq = __reduce_add_sync(0xffffffffu, ceq);
        const int needEq = K_TOP - (int)cgt;   // >= 1

        unsigned cut = 0xffffffffu;            // default: take all ties
        if ((int)ceq > needEq) {
            // keep the needEq smallest indices among ties (jax tie-break)
            unsigned l2 = 0, h2 = N_COLS - 1;
            while (l2 < h2) {
                unsigned m2 = l2 + ((h2 - l2) >> 1);
                unsigned c2 = 0;
                #pragma unroll
                for (int j = 0; j < CPL; j++) {
                    unsigned pos = (unsigned)lane + j * 32u;
                    if (key[j] == kth && sIdx[pos] <= m2) c2++;
                }
                c2 = __reduce_add_sync(0xffffffffu, c2);
                if (c2 >= (unsigned)needEq) h2 = m2; else l2 = m2 + 1;
            }
            cut = l2;
        }

        // scatter winners (all > T0 > 0, relu is identity); holes (key 0) never pass
        #pragma unroll
        for (int j = 0; j < CPL; j++) {
            unsigned k = key[j];
            if (k > kth || (k == kth && sIdx[lane + j * 32] <= cut)) {
                unsigned id = sIdx[lane + j * 32];
                orow[id] = __uint_as_float(k & 0x7fffffffu);
            }
        }
    } else {
        // ====== FALLBACK: exact warp-level full-row select (~never taken) ======
        const int NF4 = N_COLS / 4;

        unsigned lo = 0u, hi = 0xffffffffu;
        while (lo < hi) {
            unsigned mid = lo + ((hi - lo) >> 1);
            unsigned c = 0;
            for (int p = lane; p < NF4; p += 32) {
                float4 v = xr[p];
                c += (fkey(v.x) > mid) ? 1u : 0u;
                c += (fkey(v.y) > mid) ? 1u : 0u;
                c += (fkey(v.z) > mid) ? 1u : 0u;
                c += (fkey(v.w) > mid) ? 1u : 0u;
            }
            c = __reduce_add_sync(0xffffffffu, c);
            if (c < K_TOP) hi = mid; else lo = mid + 1;
        }
        const unsigned kth = lo;

        unsigned cgt = 0, ceq = 0;
        for (int p = lane; p < NF4; p += 32) {
            float4 v = xr[p];
            float vals[4] = {v.x, v.y, v.z, v.w};
            #pragma unroll
            for (int c4 = 0; c4 < 4; c4++) {
                unsigned k = fkey(vals[c4]);
                cgt += (k > kth) ? 1u : 0u;
                ceq += (k == kth) ? 1u : 0u;
            }
        }
        cgt = __reduce_add_sync(0xffffffffu, cgt);
        ceq = __reduce_add_sync(0xffffffffu, ceq);
        const int needEq = K_TOP - (int)cgt;

        unsigned cut = 0xffffffffu;
        if ((int)ceq > needEq) {
            unsigned l2 = 0, h2 = N_COLS - 1;
            while (l2 < h2) {
                unsigned m2 = l2 + ((h2 - l2) >> 1);
                unsigned c2 = 0;
                for (int p = lane; p < NF4; p += 32) {
                    float4 v = xr[p];
                    float vals[4] = {v.x, v.y, v.z, v.w};
                    #pragma unroll
                    for (int c4 = 0; c4 < 4; c4++) {
                        unsigned k = fkey(vals[c4]);
                        unsigned id = (unsigned)(p * 4 + c4);
                        if (k == kth && id <= m2) c2++;
                    }
                }
                c2 = __reduce_add_sync(0xffffffffu, c2);
                if (c2 >= (unsigned)needEq) h2 = m2; else l2 = m2 + 1;
            }
            cut = l2;
        }

        // scatter with relu (out already zeroed in phase 1)
        for (int p = lane; p < NF4; p += 32) {
            float4 v = xr[p];
            float vals[4] = {v.x, v.y, v.z, v.w};
            #pragma unroll
            for (int c4 = 0; c4 < 4; c4++) {
                unsigned k = fkey(vals[c4]);
                unsigned id = (unsigned)(p * 4 + c4);
                if (k > kth || (k == kth && id <= cut))
                    orow[id] = fmaxf(vals[c4], 0.0f);
            }
        }
    }
}

extern "C" void kernel_launch(void* const* d_in, const int* in_sizes, int n_in,
                              void* d_out, int out_size) {
    const float* x = (const float*)d_in[0];
    float* out = (float*)d_out;
    int rows = in_sizes[0] / N_COLS;   // 8192
    topk_fused<<<rows, THREADS>>>(x, out);
}

// round 14
// speedup vs baseline: 1.2691x; 1.2691x over previous
#include <cuda_runtime.h>
#include <cstdint>

#define N_COLS 24576
#define K_TOP 64
#define THREADS 512
#define F4_PER_THREAD 12   // 24576 / 4 / 512
#define CAP 512            // candidates per row (mean 341, sd ~18; +9.3 sigma)
#define CPL 16             // candidates per lane (CAP/32)
#define T0 2.2f

// Monotonic key: larger float -> larger unsigned key
__device__ __forceinline__ unsigned fkey(float x) {
    unsigned u = __float_as_uint(x);
    return (u & 0x80000000u) ? ~u : (u | 0x80000000u);
}

__global__ __launch_bounds__(THREADS, 3)
void topk_fused(const float* __restrict__ x, float* __restrict__ out) {
    __shared__ unsigned sKey[CAP];
    __shared__ unsigned sIdx[CAP];
    __shared__ unsigned s_cnt;

    const int row = blockIdx.x;
    const float4* __restrict__ xr = (const float4*)(x + (size_t)row * N_COLS);
    float4* __restrict__ orow4 = (float4*)(out + (size_t)row * N_COLS);
    float* __restrict__ orow = out + (size_t)row * N_COLS;
    const int tid = threadIdx.x;
    const int lane = tid & 31;

    if (tid == 0) s_cnt = 0;
    __syncthreads();

    const float4 zero4 = make_float4(0.f, 0.f, 0.f, 0.f);

    // ---- Phase 1: stream row, write zeros, collect candidates x > T0 to smem ----
    #pragma unroll
    for (int g = 0; g < F4_PER_THREAD / 4; g++) {
        float4 v[4];
        #pragma unroll
        for (int j = 0; j < 4; j++)
            v[j] = xr[tid + (g * 4 + j) * THREADS];

        #pragma unroll
        for (int j = 0; j < 4; j++)
            __stcs(&orow4[tid + (g * 4 + j) * THREADS], zero4);

        #pragma unroll
        for (int j = 0; j < 4; j++) {
            float m01 = fmaxf(v[j].x, v[j].y), m23 = fmaxf(v[j].z, v[j].w);
            if (fmaxf(m01, m23) > T0) {
                float vals[4] = {v[j].x, v[j].y, v[j].z, v[j].w};
                #pragma unroll
                for (int c = 0; c < 4; c++) {
                    if (vals[c] > T0) {
                        unsigned p = atomicAdd(&s_cnt, 1u);
                        if (p < CAP) {
                            sKey[p] = fkey(vals[c]);
                            sIdx[p] = (unsigned)((tid + (g * 4 + j) * THREADS) * 4 + c);
                        }
                    }
                }
            }
        }
    }
    __syncthreads();

    // ---- Phase 2: warp 0 selects + scatters; other warps retire ----
    if (tid >= 32) return;

    const unsigned nc = s_cnt;
    const unsigned T0KEY = fkey(T0);

    if (nc >= K_TOP && nc <= CAP) {
        // ============ FAST PATH (warp-local, barrier-free) ============
        const int nslot = (int)((nc + 31) >> 5);

        unsigned key[CPL];
        #pragma unroll
        for (int j = 0; j < CPL; j++) {
            unsigned pos = (unsigned)lane + j * 32u;
            key[j] = (pos < nc) ? sKey[pos] : 0u;
        }

        // warp max key -> search upper bound
        unsigned wmax = 0;
        #pragma unroll
        for (int j = 0; j < CPL; j++) wmax = max(wmax, key[j]);
        wmax = __reduce_max_sync(0xffffffffu, wmax);

        // binary search: smallest T with count(key > T) < K  ==> T = kth key
        unsigned lo = T0KEY, hi = wmax;
        while (lo < hi) {
            unsigned mid = lo + ((hi - lo) >> 1);
            unsigned c = 0;
            #pragma unroll
            for (int j = 0; j < CPL; j++) c += (key[j] > mid) ? 1u : 0u;
            c = __reduce_add_sync(0xffffffffu, c);
            if (c < K_TOP) hi = mid; else lo = mid + 1;
        }
        const unsigned kth = lo;

        unsigned cgt = 0, ceq = 0;
        #pragma unroll
        for (int j = 0; j < CPL; j++) {
            cgt += (key[j] > kth) ? 1u : 0u;
            ceq += (key[j] == kth) ? 1u : 0u;
        }
        cgt = __reduce_add_sync(0xffffffffu, cgt);
        ceq = __reduce_add_sync(0xffffffffu, ceq);
        const int needEq = K_TOP - (int)cgt;   // >= 1

        unsigned cut = 0xffffffffu;            // default: take all ties
        if ((int)ceq > needEq) {
            // keep the needEq smallest indices among ties (jax tie-break)
            unsigned l2 = 0, h2 = N_COLS - 1;
            while (l2 < h2) {
                unsigned m2 = l2 + ((h2 - l2) >> 1);
                unsigned c2 = 0;
                for (int j = 0; j < nslot; j++) {
                    unsigned pos = (unsigned)lane + j * 32u;
                    if (pos < nc && sKey[pos] == kth && sIdx[pos] <= m2) c2++;
                }
                c2 = __reduce_add_sync(0xffffffffu, c2);
                if (c2 >= (unsigned)needEq) h2 = m2; else l2 = m2 + 1;
            }
            cut = l2;
        }

        // scatter winners (all > T0 > 0, relu is identity)
        for (int j = 0; j < nslot; j++) {
            unsigned pos = (unsigned)lane + j * 32u;
            if (pos < nc) {
                unsigned k = sKey[pos];
                unsigned id = sIdx[pos];
                if (k > kth || (k == kth && id <= cut))
                    orow[id] = __uint_as_float(k & 0x7fffffffu);
            }
        }
    } else {
        // ====== FALLBACK: exact warp-level full-row select (~never taken) ======
        const int NF4 = N_COLS / 4;

        unsigned lo = 0u, hi = 0xffffffffu;
        while (lo < hi) {
            unsigned mid = lo + ((hi - lo) >> 1);
            unsigned c = 0;
            for (int p = lane; p < NF4; p += 32) {
                float4 v = xr[p];
                c += (fkey(v.x) > mid) ? 1u : 0u;
                c += (fkey(v.y) > mid) ? 1u : 0u;
                c += (fkey(v.z) > mid) ? 1u : 0u;
                c += (fkey(v.w) > mid) ? 1u : 0u;
            }
            c = __reduce_add_sync(0xffffffffu, c);
            if (c < K_TOP) hi = mid; else lo = mid + 1;
        }
        const unsigned kth = lo;

        unsigned cgt = 0, ceq = 0;
        for (int p = lane; p < NF4; p += 32) {
            float4 v = xr[p];
            float vals[4] = {v.x, v.y, v.z, v.w};
            #pragma unroll
            for (int c4 = 0; c4 < 4; c4++) {
                unsigned k = fkey(vals[c4]);
                cgt += (k > kth) ? 1u : 0u;
                ceq += (k == kth) ? 1u : 0u;
            }
        }
        cgt = __reduce_add_sync(0xffffffffu, cgt);
        ceq = __reduce_add_sync(0xffffffffu, ceq);
        const int needEq = K_TOP - (int)cgt;

        unsigned cut = 0xffffffffu;
        if ((int)ceq > needEq) {
            unsigned l2 = 0, h2 = N_COLS - 1;
            while (l2 < h2) {
                unsigned m2 = l2 + ((h2 - l2) >> 1);
                unsigned c2 = 0;
                for (int p = lane; p < NF4; p += 32) {
                    float4 v = xr[p];
                    float vals[4] = {v.x, v.y, v.z, v.w};
                    #pragma unroll
                    for (int c4 = 0; c4 < 4; c4++) {
                        unsigned k = fkey(vals[c4]);
                        unsigned id = (unsigned)(p * 4 + c4);
                        if (k == kth && id <= m2) c2++;
                    }
                }
                c2 = __reduce_add_sync(0xffffffffu, c2);
                if (c2 >= (unsigned)needEq) h2 = m2; else l2 = m2 + 1;
            }
            cut = l2;
        }

        // scatter with relu (out already zeroed in phase 1)
        for (int p = lane; p < NF4; p += 32) {
            float4 v = xr[p];
            float vals[4] = {v.x, v.y, v.z, v.w};
            #pragma unroll
            for (int c4 = 0; c4 < 4; c4++) {
                unsigned k = fkey(vals[c4]);
                unsigned id = (unsigned)(p * 4 + c4);
                if (k > kth || (k == kth && id <= cut))
                    orow[id] = fmaxf(vals[c4], 0.0f);
            }
        }
    }
}

extern "C" void kernel_launch(void* const* d_in, const int* in_sizes, int n_in,
                              void* d_out, int out_size) {
    const float* x = (const float*)d_in[0];
    float* out = (float*)d_out;
    int rows = in_sizes[0] / N_COLS;   // 8192
    topk_fused<<<rows, THREADS>>>(x, out);
}